// round 7
// baseline (speedup 1.0000x reference)
#include <cuda_runtime.h>
#include <cooperative_groups.h>
namespace cg = cooperative_groups;

#define SEQ   2048
#define INDIM 256
#define HID   256
#define G3    768

// Precomputed input projection gx[b][t][768] (includes bx). ~805 MB scratch.
__device__ float g_gx[(size_t)128 * SEQ * G3];

// ---- f32x2 packed helpers (SASS FFMA2 path, PTX-only) ----------------------
static __device__ __forceinline__ unsigned long long dup2(float a) {
    unsigned long long r;
    asm("mov.b64 %0, {%1, %1};" : "=l"(r) : "f"(a));
    return r;
}
static __device__ __forceinline__ void fma2(unsigned long long& d,
                                            unsigned long long a,
                                            unsigned long long b) {
    asm("fma.rn.f32x2 %0, %1, %2, %0;" : "+l"(d) : "l"(a), "l"(b));
}
static __device__ __forceinline__ float2 unp2(unsigned long long v) {
    float2 r;
    asm("mov.b64 {%0, %1}, %2;" : "=f"(r.x), "=f"(r.y) : "l"(v));
    return r;
}

// ---------------------------------------------------------------------------
// Phase 1: gx = x @ Wx^T + bx.  (unchanged — known good)
// ---------------------------------------------------------------------------
#define GM 128
#define GN 64
#define APAD 132
#define BPAD 68
#define GX_SMEM ((256 * APAD + 256 * BPAD) * 4)   // 204800 B

__global__ void __launch_bounds__(256, 1)
gx_gemm(const float* __restrict__ x, const float* __restrict__ Wx,
        const float* __restrict__ bx) {
    extern __shared__ float sm[];
    float* As = sm;
    float* Bs = sm + 256 * APAD;

    const int bid = blockIdx.x;
    const int mt = bid / (G3 / GN);
    const int nt = bid % (G3 / GN);
    const long m0 = (long)mt * GM;
    const int  n0 = nt * GN;
    const int tid = threadIdx.x;

    {
        const float4* src = (const float4*)(x + m0 * INDIM);
        for (int i = tid; i < GM * (INDIM / 4); i += 256) {
            float4 v = src[i];
            int m = i >> 6;
            int k = (i & 63) << 2;
            As[(k + 0) * APAD + m] = v.x;
            As[(k + 1) * APAD + m] = v.y;
            As[(k + 2) * APAD + m] = v.z;
            As[(k + 3) * APAD + m] = v.w;
        }
    }
    {
        const float4* src = (const float4*)(Wx + (long)n0 * INDIM);
        for (int i = tid; i < GN * (INDIM / 4); i += 256) {
            float4 v = src[i];
            int n = i >> 6;
            int k = (i & 63) << 2;
            Bs[(k + 0) * BPAD + n] = v.x;
            Bs[(k + 1) * BPAD + n] = v.y;
            Bs[(k + 2) * BPAD + n] = v.z;
            Bs[(k + 3) * BPAD + n] = v.w;
        }
    }
    __syncthreads();

    const int tm = (tid & 15) * 8;
    const int tn = (tid >> 4) * 4;

    unsigned long long acc[8][2];
#pragma unroll
    for (int i = 0; i < 8; i++) { acc[i][0] = 0ull; acc[i][1] = 0ull; }

#pragma unroll 8
    for (int k = 0; k < INDIM; k++) {
        float4 a0 = *(const float4*)&As[k * APAD + tm];
        float4 a1 = *(const float4*)&As[k * APAD + tm + 4];
        ulonglong2 bv = *(const ulonglong2*)&Bs[k * BPAD + tn];
        float am[8] = {a0.x, a0.y, a0.z, a0.w, a1.x, a1.y, a1.z, a1.w};
#pragma unroll
        for (int i = 0; i < 8; i++) {
            unsigned long long ad = dup2(am[i]);
            fma2(acc[i][0], ad, bv.x);
            fma2(acc[i][1], ad, bv.y);
        }
    }

    const float b0 = bx[n0 + tn + 0], b1 = bx[n0 + tn + 1];
    const float b2 = bx[n0 + tn + 2], b3 = bx[n0 + tn + 3];
#pragma unroll
    for (int i = 0; i < 8; i++) {
        float2 lo = unp2(acc[i][0]);
        float2 hi = unp2(acc[i][1]);
        float4 o;
        o.x = lo.x + b0; o.y = lo.y + b1; o.z = hi.x + b2; o.w = hi.y + b3;
        *(float4*)&g_gx[(m0 + tm + i) * G3 + n0 + tn] = o;
    }
}

// ---------------------------------------------------------------------------
// Phase 2: persistent recurrence v6 — one (row,batch) per thread.
// 32 clusters x 4 CTAs, 768 threads. CTA owns 64 hidden units (192 gate rows).
// Thread (r = tid>>2, b = tid&3) computes the FULL 256-dot for gate row r,
// batch b, k-packed in f32x2 (no dup). No mid-step reduction.
// Row pad 260 floats -> row stride 1040B == 16 (mod 128): the 8 rows of a
// warp hit 8 distinct 16B chunks => LDS.128 conflict-free, 1 wf per load.
// h stored [buf][b][260] (same trick): 4 chunks + 8x dedup => 1 wf.
// Sync: __syncthreads (gh exchange) + one cluster.sync per step (R2 pattern).
// ---------------------------------------------------------------------------
#define CLUSTER 4
#define UB    64
#define ROWS  192
#define NTHR  768
#define WPAD  260

#define OFF_HB (ROWS * WPAD)                    // 49920
#define OFF_GH (OFF_HB + 2 * 4 * WPAD)          // 52000
#define REC_SMEM ((OFF_GH + NTHR) * 4)          // 211072 B

__global__ void __launch_bounds__(NTHR, 1) __cluster_dims__(CLUSTER, 1, 1)
gru_rec(const float* __restrict__ Wh, const float* __restrict__ bh,
        const float* __restrict__ Wfc, const float* __restrict__ bfc,
        float* __restrict__ out) {
    extern __shared__ float sm[];
    float* ws   = sm;            // ws[r][260], r<192 local gate row
    float* hbuf = sm + OFF_HB;   // hbuf[buf*4 + b][260]
    float* gh   = sm + OFF_GH;   // gh[r*4 + b] == gh[tid]

    cg::cluster_group cl = cg::this_cluster();
    const int rank = (int)cl.block_rank();
    const int clid = (int)blockIdx.x / CLUSTER;
    const int tid  = threadIdx.x;
    const int U0   = rank * UB;
    const int B0   = clid * 4;

    // Load Wh slice: local row r -> global gate row (r/64)*256 + U0 + (r%64)
    for (int e4 = tid; e4 < ROWS * (HID / 4); e4 += NTHR) {
        int r = e4 >> 6;
        int k = (e4 & 63) << 2;
        int grow = (r >> 6) * HID + U0 + (r & 63);
        float4 v = *(const float4*)&Wh[(long)grow * HID + k];
        *(float4*)&ws[r * WPAD + k] = v;
    }
    for (int i = tid; i < 2 * 4 * WPAD; i += NTHR)
        hbuf[i] = 0.0f;
    __syncthreads();

    const int r = tid >> 2;             // gate row 0..191
    const int b = tid & 3;              // batch 0..3
    const ulonglong2* wv = (const ulonglong2*)(ws + r * WPAD);

    const int gu = tid & 63;            // gate-phase unit  (tid < 256)
    const int gb = (tid >> 6) & 3;      // gate-phase batch (tid < 256)
    const bool is_gate = (tid < 256);
    const float bhr = is_gate ? bh[U0 + gu]       : 0.f;
    const float bhz = is_gate ? bh[256 + U0 + gu] : 0.f;
    const float bhn = is_gate ? bh[512 + U0 + gu] : 0.f;
    float hprev = 0.0f;

    float* peer_hb[CLUSTER];
#pragma unroll
    for (int rr = 0; rr < CLUSTER; rr++)
        peer_hb[rr] = (float*)cl.map_shared_rank(hbuf, rr);

    const float* gxp = g_gx + ((long)(B0 + gb) * SEQ) * G3 + (U0 + gu);

    cl.sync();   // zeroed hbufs visible before any peer DSMEM write

    for (int t = 0; t < SEQ; t++) {
        const int cur = t & 1;
        const int nxt = cur ^ 1;

        // gx prefetch for step t (consumed in gate phase, hidden under dot)
        float gcr = 0.f, gcz = 0.f, gcn = 0.f;
        if (is_gate) {
            const float* gp = gxp + (long)t * G3;
            gcr = gp[0]; gcz = gp[256]; gcn = gp[512];
        }

        // Full 256-dot, k-packed f32x2, 4 independent accumulators
        const ulonglong2* hv = (const ulonglong2*)(hbuf + (cur * 4 + b) * WPAD);
        unsigned long long a0 = 0ull, a1 = 0ull, a2 = 0ull, a3 = 0ull;
#pragma unroll
        for (int i = 0; i < 64; i += 2) {
            ulonglong2 w0 = wv[i];
            ulonglong2 h0 = hv[i];
            ulonglong2 w1 = wv[i + 1];
            ulonglong2 h1 = hv[i + 1];
            fma2(a0, w0.x, h0.x);
            fma2(a1, w0.y, h0.y);
            fma2(a2, w1.x, h1.x);
            fma2(a3, w1.y, h1.y);
        }
        {
            float2 f0 = unp2(a0), f1 = unp2(a1), f2 = unp2(a2), f3 = unp2(a3);
            gh[tid] = ((f0.x + f0.y) + (f1.x + f1.y))
                    + ((f2.x + f2.y) + (f3.x + f3.y));
        }
        __syncthreads();

        if (is_gate) {
            float sr = gh[gu * 4 + gb]         + bhr;
            float sz = gh[(64 + gu) * 4 + gb]  + bhz;
            float sn = gh[(128 + gu) * 4 + gb] + bhn;
            float rg = __fdividef(1.0f, 1.0f + __expf(-(gcr + sr)));
            float zg = __fdividef(1.0f, 1.0f + __expf(-(gcz + sz)));
            float na = gcn + rg * sn;
            float ng = 2.0f * __fdividef(1.0f, 1.0f + __expf(-2.0f * na)) - 1.0f;
            float hnew = ng + zg * (hprev - ng);
            hprev = hnew;
            const int off = (nxt * 4 + gb) * WPAD + (U0 + gu);
#pragma unroll
            for (int rr = 0; rr < CLUSTER; rr++)
                peer_hb[rr][off] = hnew;
        }
        cl.sync();   // h(t+1) complete in every CTA
    }

    // Final h lives in hbuf[0] (t=2047: nxt=0). Rank 0 emits out[b][2].
    if (rank == 0) {
        const int w = tid >> 5, lane = tid & 31;
        if (w < 8) {
            const int bb = w >> 1, o = w & 1;
            const float* hf = hbuf + bb * WPAD;   // buf 0
            float s = 0.f;
            for (int k = lane; k < HID; k += 32)
                s += hf[k] * __ldg(&Wfc[o * HID + k]);
#pragma unroll
            for (int d = 16; d > 0; d >>= 1)
                s += __shfl_xor_sync(0xFFFFFFFFu, s, d);
            if (lane == 0)
                out[(B0 + bb) * 2 + o] = s + bfc[o];
        }
    }
}

// ---------------------------------------------------------------------------
extern "C" void kernel_launch(void* const* d_in, const int* in_sizes, int n_in,
                              void* d_out, int out_size) {
    const float* x   = (const float*)d_in[0];
    const float* Wx  = (const float*)d_in[1];
    const float* bx  = (const float*)d_in[2];
    const float* Wh  = (const float*)d_in[3];
    const float* bh  = (const float*)d_in[4];
    const float* Wfc = (const float*)d_in[5];
    const float* bfc = (const float*)d_in[6];
    float* out = (float*)d_out;

    cudaFuncSetAttribute(gx_gemm, cudaFuncAttributeMaxDynamicSharedMemorySize, GX_SMEM);
    cudaFuncSetAttribute(gru_rec, cudaFuncAttributeMaxDynamicSharedMemorySize, REC_SMEM);

    const int mtiles = (128 * SEQ) / GM;     // 2048
    const int ntiles = G3 / GN;              // 12
    gx_gemm<<<mtiles * ntiles, 256, GX_SMEM>>>(x, Wx, bx);
    gru_rec<<<32 * CLUSTER, NTHR, REC_SMEM>>>(Wh, bh, Wfc, bfc, out);
}

// round 8
// speedup vs baseline: 1.6294x; 1.6294x over previous
#include <cuda_runtime.h>
#include <cooperative_groups.h>
namespace cg = cooperative_groups;

#define SEQ   2048
#define INDIM 256
#define HID   256
#define G3    768

// Precomputed input projection gx[b][t][768] (includes bx). ~805 MB scratch.
__device__ float g_gx[(size_t)128 * SEQ * G3];

// ---- f32x2 packed helpers (SASS FFMA2 path, PTX-only) ----------------------
static __device__ __forceinline__ unsigned long long dup2(float a) {
    unsigned long long r;
    asm("mov.b64 %0, {%1, %1};" : "=l"(r) : "f"(a));
    return r;
}
static __device__ __forceinline__ void fma2(unsigned long long& d,
                                            unsigned long long a,
                                            unsigned long long b) {
    asm("fma.rn.f32x2 %0, %1, %2, %0;" : "+l"(d) : "l"(a), "l"(b));
}
static __device__ __forceinline__ float2 unp2(unsigned long long v) {
    float2 r;
    asm("mov.b64 {%0, %1}, %2;" : "=f"(r.x), "=f"(r.y) : "l"(v));
    return r;
}

// ---------------------------------------------------------------------------
// Phase 1: gx = x @ Wx^T + bx.  (unchanged — known good)
// ---------------------------------------------------------------------------
#define GM 128
#define GN 64
#define APAD 132
#define BPAD 68
#define GX_SMEM ((256 * APAD + 256 * BPAD) * 4)   // 204800 B

__global__ void __launch_bounds__(256, 1)
gx_gemm(const float* __restrict__ x, const float* __restrict__ Wx,
        const float* __restrict__ bx) {
    extern __shared__ float sm[];
    float* As = sm;
    float* Bs = sm + 256 * APAD;

    const int bid = blockIdx.x;
    const int mt = bid / (G3 / GN);
    const int nt = bid % (G3 / GN);
    const long m0 = (long)mt * GM;
    const int  n0 = nt * GN;
    const int tid = threadIdx.x;

    {
        const float4* src = (const float4*)(x + m0 * INDIM);
        for (int i = tid; i < GM * (INDIM / 4); i += 256) {
            float4 v = src[i];
            int m = i >> 6;
            int k = (i & 63) << 2;
            As[(k + 0) * APAD + m] = v.x;
            As[(k + 1) * APAD + m] = v.y;
            As[(k + 2) * APAD + m] = v.z;
            As[(k + 3) * APAD + m] = v.w;
        }
    }
    {
        const float4* src = (const float4*)(Wx + (long)n0 * INDIM);
        for (int i = tid; i < GN * (INDIM / 4); i += 256) {
            float4 v = src[i];
            int n = i >> 6;
            int k = (i & 63) << 2;
            Bs[(k + 0) * BPAD + n] = v.x;
            Bs[(k + 1) * BPAD + n] = v.y;
            Bs[(k + 2) * BPAD + n] = v.z;
            Bs[(k + 3) * BPAD + n] = v.w;
        }
    }
    __syncthreads();

    const int tm = (tid & 15) * 8;
    const int tn = (tid >> 4) * 4;

    unsigned long long acc[8][2];
#pragma unroll
    for (int i = 0; i < 8; i++) { acc[i][0] = 0ull; acc[i][1] = 0ull; }

#pragma unroll 8
    for (int k = 0; k < INDIM; k++) {
        float4 a0 = *(const float4*)&As[k * APAD + tm];
        float4 a1 = *(const float4*)&As[k * APAD + tm + 4];
        ulonglong2 bv = *(const ulonglong2*)&Bs[k * BPAD + tn];
        float am[8] = {a0.x, a0.y, a0.z, a0.w, a1.x, a1.y, a1.z, a1.w};
#pragma unroll
        for (int i = 0; i < 8; i++) {
            unsigned long long ad = dup2(am[i]);
            fma2(acc[i][0], ad, bv.x);
            fma2(acc[i][1], ad, bv.y);
        }
    }

    const float b0 = bx[n0 + tn + 0], b1 = bx[n0 + tn + 1];
    const float b2 = bx[n0 + tn + 2], b3 = bx[n0 + tn + 3];
#pragma unroll
    for (int i = 0; i < 8; i++) {
        float2 lo = unp2(acc[i][0]);
        float2 hi = unp2(acc[i][1]);
        float4 o;
        o.x = lo.x + b0; o.y = lo.y + b1; o.z = hi.x + b2; o.w = hi.y + b3;
        *(float4*)&g_gx[(m0 + tm + i) * G3 + n0 + tn] = o;
    }
}

// ---------------------------------------------------------------------------
// Phase 2: persistent recurrence v7 — phase-optimal crossbar layout.
// 32 clusters x 4 CTAs, 384 threads. CTA owns 64 units -> 192 gate rows.
// Thread (g = tid>>3, q = tid&7): rows 4g..4g+3, k-slabs k=(8s+q)*4 (s<8),
// all 4 batches, k-pair-packed f32x2 (16 accumulators).
// Every LDS phase: 8 lanes (q=0..7) read 8 consecutive distinct 16B chunks
// (both w[r][256] and h[b][256] layouts) => 128 useful B/phase everywhere.
// Partials part[q][b][row], q-stride 772 floats (3088B = 16 mod 128) =>
// conflict-free STS.128; gate reads coalesced. R2's proven sync pattern.
// ---------------------------------------------------------------------------
#define CLUSTER 4
#define UB    64
#define ROWS  192
#define NTHR  384
#define HPAD  256
#define PBLK  772

#define OFF_HB (ROWS * 256)                 // 49152: ws = 192x256
#define OFF_P  (OFF_HB + 2 * 4 * HPAD)      // 51200: hbuf = 2x4x256
#define REC_SMEM ((OFF_P + 8 * PBLK) * 4)   // 229504 B

__global__ void __launch_bounds__(NTHR, 1) __cluster_dims__(CLUSTER, 1, 1)
gru_rec(const float* __restrict__ Wh, const float* __restrict__ bh,
        const float* __restrict__ Wfc, const float* __restrict__ bfc,
        float* __restrict__ out) {
    extern __shared__ float sm[];
    float* ws   = sm;            // ws[r][256], r<192 local gate row
    float* hbuf = sm + OFF_HB;   // hbuf[buf*4 + b][256]
    float* part = sm + OFF_P;    // part[q][b*192 + row], q-stride PBLK

    cg::cluster_group cl = cg::this_cluster();
    const int rank = (int)cl.block_rank();
    const int clid = (int)blockIdx.x / CLUSTER;
    const int tid  = threadIdx.x;
    const int U0   = rank * UB;
    const int B0   = clid * 4;

    // Load Wh slice: local row r = gate*64+u -> global row gate*256 + U0 + u
    for (int e4 = tid; e4 < ROWS * (HID / 4); e4 += NTHR) {
        int r = e4 >> 6;
        int k = (e4 & 63) << 2;
        int grow = (r >> 6) * HID + U0 + (r & 63);
        *(float4*)&ws[r * 256 + k] = *(const float4*)&Wh[(long)grow * HID + k];
    }
    for (int i = tid; i < 2 * 4 * HPAD; i += NTHR)
        hbuf[i] = 0.0f;
    __syncthreads();

    const int g = tid >> 3;             // row-group 0..47 (rows 4g..4g+3)
    const int q = tid & 7;              // k-chunk
    const float* wp = ws + (g << 2) * 256;

    const int gu = tid & 63;            // gate-phase unit  (tid < 256)
    const int gb = (tid >> 6) & 3;      // gate-phase batch (tid < 256)
    const bool is_gate = (tid < 256);
    const float bhr = is_gate ? bh[U0 + gu]       : 0.f;
    const float bhz = is_gate ? bh[256 + U0 + gu] : 0.f;
    const float bhn = is_gate ? bh[512 + U0 + gu] : 0.f;
    float hprev = 0.0f;

    float* peer_hb[CLUSTER];
#pragma unroll
    for (int rr = 0; rr < CLUSTER; rr++)
        peer_hb[rr] = (float*)cl.map_shared_rank(hbuf, rr);

    const float* gxp = g_gx + ((long)(B0 + gb) * SEQ) * G3 + (U0 + gu);

    cl.sync();   // zeroed hbufs visible before any peer DSMEM write

    for (int t = 0; t < SEQ; t++) {
        const int cur = t & 1;
        const int nxt = cur ^ 1;

        // gx prefetch for step t (hidden under the dot)
        float gcr = 0.f, gcz = 0.f, gcn = 0.f;
        if (is_gate) {
            const float* gp = gxp + (long)t * G3;
            gcr = gp[0]; gcz = gp[256]; gcn = gp[512];
        }

        // Dot: 4 rows x 32 k x 4 batches, k-pair-packed. acc[b*4 + r].
        const float* hb = hbuf + cur * 4 * HPAD;
        unsigned long long acc[16];
#pragma unroll
        for (int i = 0; i < 16; i++) acc[i] = 0ull;

#pragma unroll
        for (int s = 0; s < 8; s++) {
            const int kb = (s * 8 + q) * 4;
            ulonglong2 w0 = *(const ulonglong2*)(wp + 0 * 256 + kb);
            ulonglong2 w1 = *(const ulonglong2*)(wp + 1 * 256 + kb);
            ulonglong2 w2 = *(const ulonglong2*)(wp + 2 * 256 + kb);
            ulonglong2 w3 = *(const ulonglong2*)(wp + 3 * 256 + kb);
            ulonglong2 h0 = *(const ulonglong2*)(hb + 0 * HPAD + kb);
            ulonglong2 h1 = *(const ulonglong2*)(hb + 1 * HPAD + kb);
            ulonglong2 h2 = *(const ulonglong2*)(hb + 2 * HPAD + kb);
            ulonglong2 h3 = *(const ulonglong2*)(hb + 3 * HPAD + kb);
            fma2(acc[0],  w0.x, h0.x); fma2(acc[0],  w0.y, h0.y);
            fma2(acc[1],  w1.x, h0.x); fma2(acc[1],  w1.y, h0.y);
            fma2(acc[2],  w2.x, h0.x); fma2(acc[2],  w2.y, h0.y);
            fma2(acc[3],  w3.x, h0.x); fma2(acc[3],  w3.y, h0.y);
            fma2(acc[4],  w0.x, h1.x); fma2(acc[4],  w0.y, h1.y);
            fma2(acc[5],  w1.x, h1.x); fma2(acc[5],  w1.y, h1.y);
            fma2(acc[6],  w2.x, h1.x); fma2(acc[6],  w2.y, h1.y);
            fma2(acc[7],  w3.x, h1.x); fma2(acc[7],  w3.y, h1.y);
            fma2(acc[8],  w0.x, h2.x); fma2(acc[8],  w0.y, h2.y);
            fma2(acc[9],  w1.x, h2.x); fma2(acc[9],  w1.y, h2.y);
            fma2(acc[10], w2.x, h2.x); fma2(acc[10], w2.y, h2.y);
            fma2(acc[11], w3.x, h2.x); fma2(acc[11], w3.y, h2.y);
            fma2(acc[12], w0.x, h3.x); fma2(acc[12], w0.y, h3.y);
            fma2(acc[13], w1.x, h3.x); fma2(acc[13], w1.y, h3.y);
            fma2(acc[14], w2.x, h3.x); fma2(acc[14], w2.y, h3.y);
            fma2(acc[15], w3.x, h3.x); fma2(acc[15], w3.y, h3.y);
        }

        // Horizontal k-pair sum, store 4 rows per batch as one STS.128
        {
            float* pq = part + q * PBLK + (g << 2);
#pragma unroll
            for (int b = 0; b < 4; b++) {
                float2 f0 = unp2(acc[b * 4 + 0]);
                float2 f1 = unp2(acc[b * 4 + 1]);
                float2 f2 = unp2(acc[b * 4 + 2]);
                float2 f3 = unp2(acc[b * 4 + 3]);
                float4 o;
                o.x = f0.x + f0.y; o.y = f1.x + f1.y;
                o.z = f2.x + f2.y; o.w = f3.x + f3.y;
                *(float4*)(pq + b * 192) = o;
            }
        }
        __syncthreads();

        if (is_gate) {
            float sr = bhr, sz = bhz, sn = bhn;
#pragma unroll
            for (int qq = 0; qq < 8; qq++) {
                const float* pq = part + qq * PBLK + gb * 192;
                sr += pq[gu];
                sz += pq[64 + gu];
                sn += pq[128 + gu];
            }
            float rg = __fdividef(1.0f, 1.0f + __expf(-(gcr + sr)));
            float zg = __fdividef(1.0f, 1.0f + __expf(-(gcz + sz)));
            float na = gcn + rg * sn;
            float ng = 2.0f * __fdividef(1.0f, 1.0f + __expf(-2.0f * na)) - 1.0f;
            float hnew = ng + zg * (hprev - ng);
            hprev = hnew;
            const int off = (nxt * 4 + gb) * HPAD + (U0 + gu);
#pragma unroll
            for (int rr = 0; rr < CLUSTER; rr++)
                peer_hb[rr][off] = hnew;
        }
        cl.sync();   // h(t+1) complete in every CTA
    }

    // Final h lives in hbuf[0] (t=2047: nxt=0). Rank 0 emits out[b][2].
    if (rank == 0) {
        const int w = tid >> 5, lane = tid & 31;
        if (w < 8) {
            const int bb = w >> 1, o = w & 1;
            const float* hf = hbuf + bb * HPAD;   // buf 0
            float s = 0.f;
            for (int k = lane; k < HID; k += 32)
                s += hf[k] * __ldg(&Wfc[o * HID + k]);
#pragma unroll
            for (int d = 16; d > 0; d >>= 1)
                s += __shfl_xor_sync(0xFFFFFFFFu, s, d);
            if (lane == 0)
                out[(B0 + bb) * 2 + o] = s + bfc[o];
        }
    }
}

// ---------------------------------------------------------------------------
extern "C" void kernel_launch(void* const* d_in, const int* in_sizes, int n_in,
                              void* d_out, int out_size) {
    const float* x   = (const float*)d_in[0];
    const float* Wx  = (const float*)d_in[1];
    const float* bx  = (const float*)d_in[2];
    const float* Wh  = (const float*)d_in[3];
    const float* bh  = (const float*)d_in[4];
    const float* Wfc = (const float*)d_in[5];
    const float* bfc = (const float*)d_in[6];
    float* out = (float*)d_out;

    cudaFuncSetAttribute(gx_gemm, cudaFuncAttributeMaxDynamicSharedMemorySize, GX_SMEM);
    cudaFuncSetAttribute(gru_rec, cudaFuncAttributeMaxDynamicSharedMemorySize, REC_SMEM);

    const int mtiles = (128 * SEQ) / GM;     // 2048
    const int ntiles = G3 / GN;              // 12
    gx_gemm<<<mtiles * ntiles, 256, GX_SMEM>>>(x, Wx, bx);
    gru_rec<<<32 * CLUSTER, NTHR, REC_SMEM>>>(Wh, bh, Wfc, bfc, out);
}

// round 9
// speedup vs baseline: 2.3637x; 1.4507x over previous
#include <cuda_runtime.h>
#include <cooperative_groups.h>
namespace cg = cooperative_groups;

#define SEQ   2048
#define INDIM 256
#define HID   256
#define G3    768

// Precomputed input projection gx[b][t][768] (includes bx). ~805 MB scratch.
__device__ float g_gx[(size_t)128 * SEQ * G3];

// ---- f32x2 packed helpers (SASS FFMA2 path, PTX-only) ----------------------
static __device__ __forceinline__ unsigned long long dup2(float a) {
    unsigned long long r;
    asm("mov.b64 %0, {%1, %1};" : "=l"(r) : "f"(a));
    return r;
}
static __device__ __forceinline__ void fma2(unsigned long long& d,
                                            unsigned long long a,
                                            unsigned long long b) {
    asm("fma.rn.f32x2 %0, %1, %2, %0;" : "+l"(d) : "l"(a), "l"(b));
}
static __device__ __forceinline__ float2 unp2(unsigned long long v) {
    float2 r;
    asm("mov.b64 {%0, %1}, %2;" : "=f"(r.x), "=f"(r.y) : "l"(v));
    return r;
}
static __device__ __forceinline__ unsigned smem_u32(const void* p) {
    return (unsigned)__cvta_generic_to_shared(p);
}
static __device__ __forceinline__ void cp_async4(unsigned dst, const void* src) {
    asm volatile("cp.async.ca.shared.global [%0], [%1], 4;" :: "r"(dst), "l"(src));
}
static __device__ __forceinline__ void cp_commit() {
    asm volatile("cp.async.commit_group;" ::: "memory");
}
template <int N>
static __device__ __forceinline__ void cp_wait() {
    asm volatile("cp.async.wait_group %0;" :: "n"(N) : "memory");
}

// ---------------------------------------------------------------------------
// Phase 1 v2: gx = x @ Wx^T + bx.
// BM=128, BN=128, BK=32, 256 threads, 8x8 microtile (f32x2, m-packed),
// cp.async 4B transposing loads (As[k][132], Bs[k][132]), double-buffered,
// ~67.6KB smem + ~116 regs -> 2 CTAs/SM.
// ---------------------------------------------------------------------------
#define GXP 132                       // k-row stride (words) for As/Bs
#define GX_BUF (32 * GXP)             // 4224 words per buffer
#define GX_SMEM (4 * GX_BUF * 4)      // A0,A1,B0,B1 = 67584 B

__global__ void __launch_bounds__(256, 2)
gx_gemm(const float* __restrict__ x, const float* __restrict__ Wx,
        const float* __restrict__ bx) {
    extern __shared__ float sm[];
    float* As = sm;                   // As[buf][k][m]
    float* Bs = sm + 2 * GX_BUF;      // Bs[buf][k][n]

    const int bid = blockIdx.x;
    const int mt = bid / 6;
    const int nt = bid % 6;
    const long m0 = (long)mt * 128;
    const int  n0 = nt * 128;
    const int tid = threadIdx.x;
    const int wid = tid >> 5;
    const int lane = tid & 31;

    const unsigned sA = smem_u32(As);
    const unsigned sB = smem_u32(Bs);

    // chunk loader: rows (wid*16 + i), lane = k within chunk
    auto load_chunk = [&](int c) {
        const int buf = c & 1;
        const int k0 = c * 32;
        const unsigned dA = sA + (buf * GX_BUF + lane * GXP) * 4;
        const unsigned dB = sB + (buf * GX_BUF + lane * GXP) * 4;
        const float* gA = x + (m0 + wid * 16) * INDIM + k0 + lane;
        const float* gB = Wx + (long)(n0 + wid * 16) * INDIM + k0 + lane;
#pragma unroll
        for (int i = 0; i < 16; i++) {
            int row = wid * 16 + i;
            cp_async4(dA + row * 4, gA + i * INDIM);
            cp_async4(dB + row * 4, gB + i * INDIM);
        }
        cp_commit();
    };

    load_chunk(0);
    load_chunk(1);

    const int tm = (tid & 15) * 8;
    const int tn = (tid >> 4) * 8;

    unsigned long long acc[4][8];
#pragma unroll
    for (int i = 0; i < 4; i++)
#pragma unroll
        for (int j = 0; j < 8; j++) acc[i][j] = 0ull;

#pragma unroll 1
    for (int c = 0; c < 8; c++) {
        if (c < 6) cp_wait<1>(); else cp_wait<0>();
        __syncthreads();

        const float* ab = As + (c & 1) * GX_BUF;
        const float* bb = Bs + (c & 1) * GX_BUF;
#pragma unroll 8
        for (int k = 0; k < 32; k++) {
            ulonglong2 a0 = *(const ulonglong2*)(ab + k * GXP + tm);
            ulonglong2 a1 = *(const ulonglong2*)(ab + k * GXP + tm + 4);
            float4 b0 = *(const float4*)(bb + k * GXP + tn);
            float4 b1 = *(const float4*)(bb + k * GXP + tn + 4);
            unsigned long long am[4] = {a0.x, a0.y, a1.x, a1.y};
            float bn[8] = {b0.x, b0.y, b0.z, b0.w, b1.x, b1.y, b1.z, b1.w};
#pragma unroll
            for (int j = 0; j < 8; j++) {
                unsigned long long bd = dup2(bn[j]);
#pragma unroll
                for (int i = 0; i < 4; i++)
                    fma2(acc[i][j], am[i], bd);
            }
        }
        __syncthreads();
        if (c + 2 < 8) load_chunk(c + 2);
    }

    // epilogue: bias + store (rows tm+2i, tm+2i+1; cols tn..tn+7)
    float bn[8];
#pragma unroll
    for (int j = 0; j < 8; j++) bn[j] = bx[n0 + tn + j];
#pragma unroll
    for (int i = 0; i < 4; i++) {
        float lo[8], hi[8];
#pragma unroll
        for (int j = 0; j < 8; j++) {
            float2 f = unp2(acc[i][j]);
            lo[j] = f.x + bn[j];
            hi[j] = f.y + bn[j];
        }
        float* r0 = &g_gx[(m0 + tm + 2 * i) * G3 + n0 + tn];
        float* r1 = r0 + G3;
        *(float4*)(r0)     = make_float4(lo[0], lo[1], lo[2], lo[3]);
        *(float4*)(r0 + 4) = make_float4(lo[4], lo[5], lo[6], lo[7]);
        *(float4*)(r1)     = make_float4(hi[0], hi[1], hi[2], hi[3]);
        *(float4*)(r1 + 4) = make_float4(hi[4], hi[5], hi[6], hi[7]);
    }
}

// ---------------------------------------------------------------------------
// Phase 2: persistent recurrence v7 (UNCHANGED from round 7 — best known).
// ---------------------------------------------------------------------------
#define CLUSTER 4
#define UB    64
#define ROWS  192
#define NTHR  384
#define HPAD  256
#define PBLK  772

#define OFF_HB (ROWS * 256)                 // 49152: ws = 192x256
#define OFF_P  (OFF_HB + 2 * 4 * HPAD)      // 51200: hbuf = 2x4x256
#define REC_SMEM ((OFF_P + 8 * PBLK) * 4)   // 229504 B

__global__ void __launch_bounds__(NTHR, 1) __cluster_dims__(CLUSTER, 1, 1)
gru_rec(const float* __restrict__ Wh, const float* __restrict__ bh,
        const float* __restrict__ Wfc, const float* __restrict__ bfc,
        float* __restrict__ out) {
    extern __shared__ float sm[];
    float* ws   = sm;            // ws[r][256], r<192 local gate row
    float* hbuf = sm + OFF_HB;   // hbuf[buf*4 + b][256]
    float* part = sm + OFF_P;    // part[q][b*192 + row], q-stride PBLK

    cg::cluster_group cl = cg::this_cluster();
    const int rank = (int)cl.block_rank();
    const int clid = (int)blockIdx.x / CLUSTER;
    const int tid  = threadIdx.x;
    const int U0   = rank * UB;
    const int B0   = clid * 4;

    for (int e4 = tid; e4 < ROWS * (HID / 4); e4 += NTHR) {
        int r = e4 >> 6;
        int k = (e4 & 63) << 2;
        int grow = (r >> 6) * HID + U0 + (r & 63);
        *(float4*)&ws[r * 256 + k] = *(const float4*)&Wh[(long)grow * HID + k];
    }
    for (int i = tid; i < 2 * 4 * HPAD; i += NTHR)
        hbuf[i] = 0.0f;
    __syncthreads();

    const int g = tid >> 3;             // row-group 0..47 (rows 4g..4g+3)
    const int q = tid & 7;              // k-chunk
    const float* wp = ws + (g << 2) * 256;

    const int gu = tid & 63;
    const int gb = (tid >> 6) & 3;
    const bool is_gate = (tid < 256);
    const float bhr = is_gate ? bh[U0 + gu]       : 0.f;
    const float bhz = is_gate ? bh[256 + U0 + gu] : 0.f;
    const float bhn = is_gate ? bh[512 + U0 + gu] : 0.f;
    float hprev = 0.0f;

    float* peer_hb[CLUSTER];
#pragma unroll
    for (int rr = 0; rr < CLUSTER; rr++)
        peer_hb[rr] = (float*)cl.map_shared_rank(hbuf, rr);

    const float* gxp = g_gx + ((long)(B0 + gb) * SEQ) * G3 + (U0 + gu);

    cl.sync();

    for (int t = 0; t < SEQ; t++) {
        const int cur = t & 1;
        const int nxt = cur ^ 1;

        float gcr = 0.f, gcz = 0.f, gcn = 0.f;
        if (is_gate) {
            const float* gp = gxp + (long)t * G3;
            gcr = gp[0]; gcz = gp[256]; gcn = gp[512];
        }

        const float* hb = hbuf + cur * 4 * HPAD;
        unsigned long long acc[16];
#pragma unroll
        for (int i = 0; i < 16; i++) acc[i] = 0ull;

#pragma unroll
        for (int s = 0; s < 8; s++) {
            const int kb = (s * 8 + q) * 4;
            ulonglong2 w0 = *(const ulonglong2*)(wp + 0 * 256 + kb);
            ulonglong2 w1 = *(const ulonglong2*)(wp + 1 * 256 + kb);
            ulonglong2 w2 = *(const ulonglong2*)(wp + 2 * 256 + kb);
            ulonglong2 w3 = *(const ulonglong2*)(wp + 3 * 256 + kb);
            ulonglong2 h0 = *(const ulonglong2*)(hb + 0 * HPAD + kb);
            ulonglong2 h1 = *(const ulonglong2*)(hb + 1 * HPAD + kb);
            ulonglong2 h2 = *(const ulonglong2*)(hb + 2 * HPAD + kb);
            ulonglong2 h3 = *(const ulonglong2*)(hb + 3 * HPAD + kb);
            fma2(acc[0],  w0.x, h0.x); fma2(acc[0],  w0.y, h0.y);
            fma2(acc[1],  w1.x, h0.x); fma2(acc[1],  w1.y, h0.y);
            fma2(acc[2],  w2.x, h0.x); fma2(acc[2],  w2.y, h0.y);
            fma2(acc[3],  w3.x, h0.x); fma2(acc[3],  w3.y, h0.y);
            fma2(acc[4],  w0.x, h1.x); fma2(acc[4],  w0.y, h1.y);
            fma2(acc[5],  w1.x, h1.x); fma2(acc[5],  w1.y, h1.y);
            fma2(acc[6],  w2.x, h1.x); fma2(acc[6],  w2.y, h1.y);
            fma2(acc[7],  w3.x, h1.x); fma2(acc[7],  w3.y, h1.y);
            fma2(acc[8],  w0.x, h2.x); fma2(acc[8],  w0.y, h2.y);
            fma2(acc[9],  w1.x, h2.x); fma2(acc[9],  w1.y, h2.y);
            fma2(acc[10], w2.x, h2.x); fma2(acc[10], w2.y, h2.y);
            fma2(acc[11], w3.x, h2.x); fma2(acc[11], w3.y, h2.y);
            fma2(acc[12], w0.x, h3.x); fma2(acc[12], w0.y, h3.y);
            fma2(acc[13], w1.x, h3.x); fma2(acc[13], w1.y, h3.y);
            fma2(acc[14], w2.x, h3.x); fma2(acc[14], w2.y, h3.y);
            fma2(acc[15], w3.x, h3.x); fma2(acc[15], w3.y, h3.y);
        }

        {
            float* pq = part + q * PBLK + (g << 2);
#pragma unroll
            for (int b = 0; b < 4; b++) {
                float2 f0 = unp2(acc[b * 4 + 0]);
                float2 f1 = unp2(acc[b * 4 + 1]);
                float2 f2 = unp2(acc[b * 4 + 2]);
                float2 f3 = unp2(acc[b * 4 + 3]);
                float4 o;
                o.x = f0.x + f0.y; o.y = f1.x + f1.y;
                o.z = f2.x + f2.y; o.w = f3.x + f3.y;
                *(float4*)(pq + b * 192) = o;
            }
        }
        __syncthreads();

        if (is_gate) {
            float sr = bhr, sz = bhz, sn = bhn;
#pragma unroll
            for (int qq = 0; qq < 8; qq++) {
                const float* pq = part + qq * PBLK + gb * 192;
                sr += pq[gu];
                sz += pq[64 + gu];
                sn += pq[128 + gu];
            }
            float rg = __fdividef(1.0f, 1.0f + __expf(-(gcr + sr)));
            float zg = __fdividef(1.0f, 1.0f + __expf(-(gcz + sz)));
            float na = gcn + rg * sn;
            float ng = 2.0f * __fdividef(1.0f, 1.0f + __expf(-2.0f * na)) - 1.0f;
            float hnew = ng + zg * (hprev - ng);
            hprev = hnew;
            const int off = (nxt * 4 + gb) * HPAD + (U0 + gu);
#pragma unroll
            for (int rr = 0; rr < CLUSTER; rr++)
                peer_hb[rr][off] = hnew;
        }
        cl.sync();
    }

    if (rank == 0) {
        const int w = tid >> 5, lane = tid & 31;
        if (w < 8) {
            const int bb = w >> 1, o = w & 1;
            const float* hf = hbuf + bb * HPAD;
            float s = 0.f;
            for (int k = lane; k < HID; k += 32)
                s += hf[k] * __ldg(&Wfc[o * HID + k]);
#pragma unroll
            for (int d = 16; d > 0; d >>= 1)
                s += __shfl_xor_sync(0xFFFFFFFFu, s, d);
            if (lane == 0)
                out[(B0 + bb) * 2 + o] = s + bfc[o];
        }
    }
}

// ---------------------------------------------------------------------------
extern "C" void kernel_launch(void* const* d_in, const int* in_sizes, int n_in,
                              void* d_out, int out_size) {
    const float* x   = (const float*)d_in[0];
    const float* Wx  = (const float*)d_in[1];
    const float* bx  = (const float*)d_in[2];
    const float* Wh  = (const float*)d_in[3];
    const float* bh  = (const float*)d_in[4];
    const float* Wfc = (const float*)d_in[5];
    const float* bfc = (const float*)d_in[6];
    float* out = (float*)d_out;

    cudaFuncSetAttribute(gx_gemm, cudaFuncAttributeMaxDynamicSharedMemorySize, GX_SMEM);
    cudaFuncSetAttribute(gru_rec, cudaFuncAttributeMaxDynamicSharedMemorySize, REC_SMEM);

    const int mtiles = (128 * SEQ) / 128;    // 2048
    const int ntiles = G3 / 128;             // 6
    gx_gemm<<<mtiles * ntiles, 256, GX_SMEM>>>(x, Wx, bx);
    gru_rec<<<32 * CLUSTER, NTHR, REC_SMEM>>>(Wh, bh, Wfc, bfc, out);
}